// round 7
// baseline (speedup 1.0000x reference)
#include <cuda_runtime.h>
#include <cstdint>

// ---------------- problem constants (fixed by dataset) ----------------
#define MAXN 100000
#define MAXE 1600000
#define FIN  128
#define HID  64
#define FOUT 32

// ---------------- device scratch (static: no allocs allowed) ----------
__device__ float g_ha[MAXN * HID];        // GEMM output / agg input
__device__ float g_hb[MAXN * HID];        // agg output (relu'd)
__device__ int   g_src[MAXE];
__device__ int   g_dst[MAXE];
__device__ int   g_csr_src[MAXE];
__device__ float g_csr_norm[MAXE];
__device__ float g_deg[MAXN];
__device__ float g_dinv[MAXN];
__device__ int   g_cnt[MAXN];
__device__ int   g_fill[MAXN];
__device__ int   g_rowptr[MAXN + 1];
__device__ float g_pool[256 * FOUT];
__device__ int   g_flag;                  // 1 if edge_index is int64 layout

// ---------------- dtype detection for edge_index ----------------------
// If the buffer is int64 (values < 2^31, nonneg), every odd int32 word is 0.
// If it is int32 edge data, odd words are random node ids (~never all zero).
__global__ void detect_kernel(const int* __restrict__ ei32) {
    if (threadIdx.x == 0 && blockIdx.x == 0) {
        int zeros = 0;
        for (int i = 0; i < 256; i++)
            if (ei32[2 * i + 1] == 0) zeros++;
        g_flag = (zeros == 256) ? 1 : 0;
    }
}

// ---------------- init ------------------------------------------------
__global__ void init_kernel(int N) {
    int i = blockIdx.x * blockDim.x + threadIdx.x;
    if (i < N) {
        g_deg[i] = 1.0f;   // self-loop weight
        g_cnt[i] = 0;
        g_fill[i] = 0;
    }
}

// ---------------- pass 1: degree + counts + int32 conversion ----------
__global__ void edge_pass_kernel(const void* __restrict__ eidx,
                                 const float* __restrict__ ew, int E) {
    int e = blockIdx.x * blockDim.x + threadIdx.x;
    if (e >= E) return;
    int s, d;
    if (g_flag) {
        const long long* p = (const long long*)eidx;
        s = (int)p[e];
        d = (int)p[E + e];
    } else {
        const int* p = (const int*)eidx;
        s = p[e];
        d = p[E + e];
    }
    g_src[e] = s;
    g_dst[e] = d;
    atomicAdd(&g_deg[d], ew[e]);
    atomicAdd(&g_cnt[d], 1);
}

__global__ void dinv_kernel(int N) {
    int i = blockIdx.x * blockDim.x + threadIdx.x;
    if (i < N) {
        float dg = g_deg[i];
        g_dinv[i] = (dg > 0.0f) ? rsqrtf(dg) : 0.0f;
    }
}

// ---------------- exclusive scan of g_cnt -> g_rowptr ------------------
// single block, 1024 threads, 4 elems/thread per chunk, warp-shuffle scans.
__global__ void scan_kernel(int N) {
    __shared__ int sh[32];
    int tid = threadIdx.x;
    int lane = tid & 31, wid = tid >> 5;
    int carry = 0;
    const int CH = 4096;
    for (int base = 0; base < N; base += CH) {
        int idx = base + tid * 4;
        int v0 = (idx + 0 < N) ? g_cnt[idx + 0] : 0;
        int v1 = (idx + 1 < N) ? g_cnt[idx + 1] : 0;
        int v2 = (idx + 2 < N) ? g_cnt[idx + 2] : 0;
        int v3 = (idx + 3 < N) ? g_cnt[idx + 3] : 0;
        int p0 = v0, p1 = p0 + v1, p2 = p1 + v2, p3 = p2 + v3;
        int t = p3;
        #pragma unroll
        for (int o = 1; o < 32; o <<= 1) {
            int u = __shfl_up_sync(0xFFFFFFFFu, t, o);
            if (lane >= o) t += u;
        }
        if (lane == 31) sh[wid] = t;
        __syncthreads();
        if (wid == 0) {
            int s = sh[lane];
            #pragma unroll
            for (int o = 1; o < 32; o <<= 1) {
                int u = __shfl_up_sync(0xFFFFFFFFu, s, o);
                if (lane >= o) s += u;
            }
            sh[lane] = s;
        }
        __syncthreads();
        int woff = (wid > 0) ? sh[wid - 1] : 0;
        int off = carry + woff + (t - p3);   // exclusive base for this thread
        if (idx + 0 < N) g_rowptr[idx + 0] = off;
        if (idx + 1 < N) g_rowptr[idx + 1] = off + p0;
        if (idx + 2 < N) g_rowptr[idx + 2] = off + p1;
        if (idx + 3 < N) g_rowptr[idx + 3] = off + p2;
        int total = sh[31];
        __syncthreads();
        carry += total;
    }
    if (tid == 0) g_rowptr[N] = carry;
}

// ---------------- pass 2: CSR fill (bucket order irrelevant) ----------
__global__ void fill_kernel(const float* __restrict__ ew, int E) {
    int e = blockIdx.x * blockDim.x + threadIdx.x;
    if (e >= E) return;
    int s = g_src[e];
    int d = g_dst[e];
    int pos = g_rowptr[d] + atomicAdd(&g_fill[d], 1);
    g_csr_src[pos] = s;
    g_csr_norm[pos] = g_dinv[s] * ew[e] * g_dinv[d];
}

// ---------------- fp32 SGEMM: C[N,NOUT] = A[N,K] @ W[K,NOUT] -----------
// BM=128 rows/block, 256 threads, thread tile TM x 4, K chunked by 16.
template <int K, int NOUT, int TM>
__global__ __launch_bounds__(256) void gemm_kernel(
    const float* __restrict__ A, const float* __restrict__ W,
    float* __restrict__ C, int N) {
    constexpr int BM = 128, TN = 4, KC = 16;
    constexpr int NCOL = NOUT / TN;
    __shared__ float xs[KC][BM];
    __shared__ float ws[KC][NOUT];
    int tid = threadIdx.x;
    int tcol = tid % NCOL, trow = tid / NCOL;
    int r0 = blockIdx.x * BM;
    int lrow = tid >> 1, half = tid & 1;

    float acc[TM][TN];
    #pragma unroll
    for (int i = 0; i < TM; i++)
        #pragma unroll
        for (int j = 0; j < TN; j++) acc[i][j] = 0.0f;

    for (int k0 = 0; k0 < K; k0 += KC) {
        // load A tile transposed: xs[kk][row]
        int grow = r0 + lrow;
        float4 u0 = make_float4(0, 0, 0, 0), u1 = make_float4(0, 0, 0, 0);
        if (grow < N) {
            const float4* xp =
                (const float4*)(A + (size_t)grow * K + k0 + half * 8);
            u0 = xp[0];
            u1 = xp[1];
        }
        int kb = half * 8;
        xs[kb + 0][lrow] = u0.x; xs[kb + 1][lrow] = u0.y;
        xs[kb + 2][lrow] = u0.z; xs[kb + 3][lrow] = u0.w;
        xs[kb + 4][lrow] = u1.x; xs[kb + 5][lrow] = u1.y;
        xs[kb + 6][lrow] = u1.z; xs[kb + 7][lrow] = u1.w;
        // load W tile
        constexpr int NF4 = KC * NOUT / 4;
        if (tid < NF4) {
            int kk = tid / (NOUT / 4);
            int c = (tid % (NOUT / 4)) * 4;
            *(float4*)&ws[kk][c] =
                *(const float4*)(W + (size_t)(k0 + kk) * NOUT + c);
        }
        __syncthreads();
        #pragma unroll
        for (int kk = 0; kk < KC; kk++) {
            float4 b4 = *(float4*)&ws[kk][tcol * TN];
            float a[TM];
            #pragma unroll
            for (int i = 0; i < TM; i += 4) {
                float4 a4 = *(float4*)&xs[kk][trow * TM + i];
                a[i] = a4.x; a[i + 1] = a4.y; a[i + 2] = a4.z; a[i + 3] = a4.w;
            }
            #pragma unroll
            for (int i = 0; i < TM; i++) {
                acc[i][0] += a[i] * b4.x;
                acc[i][1] += a[i] * b4.y;
                acc[i][2] += a[i] * b4.z;
                acc[i][3] += a[i] * b4.w;
            }
        }
        __syncthreads();
    }
    #pragma unroll
    for (int i = 0; i < TM; i++) {
        int grow = r0 + trow * TM + i;
        if (grow < N) {
            *(float4*)(C + (size_t)grow * NOUT + tcol * TN) =
                make_float4(acc[i][0], acc[i][1], acc[i][2], acc[i][3]);
        }
    }
}

// ---------------- aggregation: out[i] = relu?(sum_e norm*h[src] + self + b)
// one warp per node; NF=64 -> float2/lane, NF=32 -> float/lane.
// 4-deep MLP unroll to hide L2 latency.
template <int NF, bool RELU>
__global__ __launch_bounds__(256) void agg_kernel(
    const float* __restrict__ h, const float* __restrict__ bias,
    float* __restrict__ out, int N) {
    int warp = (blockIdx.x * blockDim.x + threadIdx.x) >> 5;
    int lane = threadIdx.x & 31;
    if (warp >= N) return;
    constexpr int FPL = NF / 32;
    float di = g_dinv[warp];
    float sw = di * di;

    float acc0, acc1 = 0.0f;
    const float* hrow = h + (size_t)warp * NF + lane * FPL;
    if (FPL == 2) {
        float2 v = *(const float2*)hrow;
        acc0 = sw * v.x;
        acc1 = sw * v.y;
    } else {
        acc0 = sw * hrow[0];
    }

    int e = g_rowptr[warp];
    int end = g_rowptr[warp + 1];
    for (; e + 4 <= end; e += 4) {
        int s0 = g_csr_src[e + 0], s1 = g_csr_src[e + 1];
        int s2 = g_csr_src[e + 2], s3 = g_csr_src[e + 3];
        float w0 = g_csr_norm[e + 0], w1 = g_csr_norm[e + 1];
        float w2 = g_csr_norm[e + 2], w3 = g_csr_norm[e + 3];
        if (FPL == 2) {
            float2 v0 = *(const float2*)(h + (size_t)s0 * NF + lane * 2);
            float2 v1 = *(const float2*)(h + (size_t)s1 * NF + lane * 2);
            float2 v2 = *(const float2*)(h + (size_t)s2 * NF + lane * 2);
            float2 v3 = *(const float2*)(h + (size_t)s3 * NF + lane * 2);
            acc0 += w0 * v0.x; acc1 += w0 * v0.y;
            acc0 += w1 * v1.x; acc1 += w1 * v1.y;
            acc0 += w2 * v2.x; acc1 += w2 * v2.y;
            acc0 += w3 * v3.x; acc1 += w3 * v3.y;
        } else {
            float v0 = h[(size_t)s0 * NF + lane];
            float v1 = h[(size_t)s1 * NF + lane];
            float v2 = h[(size_t)s2 * NF + lane];
            float v3 = h[(size_t)s3 * NF + lane];
            acc0 += w0 * v0 + w1 * v1 + w2 * v2 + w3 * v3;
        }
    }
    for (; e < end; e++) {
        int s = g_csr_src[e];
        float w = g_csr_norm[e];
        if (FPL == 2) {
            float2 v = *(const float2*)(h + (size_t)s * NF + lane * 2);
            acc0 += w * v.x;
            acc1 += w * v.y;
        } else {
            acc0 += w * h[(size_t)s * NF + lane];
        }
    }

    float* orow = out + (size_t)warp * NF + lane * FPL;
    if (FPL == 2) {
        float r0 = acc0 + bias[lane * 2 + 0];
        float r1 = acc1 + bias[lane * 2 + 1];
        if (RELU) { r0 = fmaxf(r0, 0.0f); r1 = fmaxf(r1, 0.0f); }
        float2 r; r.x = r0; r.y = r1;
        *(float2*)orow = r;
    } else {
        float r0 = acc0 + bias[lane];
        if (RELU) r0 = fmaxf(r0, 0.0f);
        orow[0] = r0;
    }
}

// ---------------- mean pool over node embeddings -----------------------
__global__ void pool1_kernel(const float* __restrict__ emb, int N) {
    __shared__ float sh[256];
    int tid = threadIdx.x;
    int g = blockIdx.x * 256 + tid;
    const int G = 256 * 256;           // G % 32 == 0 -> feature is g % 32
    float s = 0.0f;
    int total = N * FOUT;
    for (int i = g; i < total; i += G) s += emb[i];
    sh[tid] = s;
    __syncthreads();
    if (tid < FOUT) {
        float t = 0.0f;
        #pragma unroll
        for (int j = 0; j < 256 / FOUT; j++) t += sh[tid + j * FOUT];
        g_pool[blockIdx.x * FOUT + tid] = t;
    }
}

__global__ void pool2_kernel(float* __restrict__ out, int N) {
    int f = threadIdx.x;
    if (f < FOUT) {
        float s = 0.0f;
        for (int b = 0; b < 256; b++) s += g_pool[b * FOUT + f];
        out[(size_t)N * FOUT + f] = s / (float)N;
    }
}

// ---------------- launch ------------------------------------------------
static inline int cdiv(int a, int b) { return (a + b - 1) / b; }

extern "C" void kernel_launch(void* const* d_in, const int* in_sizes, int n_in,
                              void* d_out, int out_size) {
    const float* x  = (const float*)d_in[0];
    const void*  ei = d_in[1];
    const float* ew = (const float*)d_in[2];
    const float* W1 = (const float*)d_in[3];
    const float* b1 = (const float*)d_in[4];
    const float* W2 = (const float*)d_in[5];
    const float* b2 = (const float*)d_in[6];
    const float* W3 = (const float*)d_in[7];
    const float* b3 = (const float*)d_in[8];
    float* out = (float*)d_out;

    int E = in_sizes[2];
    int N = in_sizes[0] / FIN;
    if (N > MAXN) N = MAXN;
    if (E > MAXE) E = MAXE;

    float *p_ha, *p_hb;
    cudaGetSymbolAddress((void**)&p_ha, g_ha);
    cudaGetSymbolAddress((void**)&p_hb, g_hb);

    // ---- preprocessing: norm + CSR ----
    detect_kernel<<<1, 32>>>((const int*)ei);
    init_kernel<<<cdiv(N, 256), 256>>>(N);
    edge_pass_kernel<<<cdiv(E, 256), 256>>>(ei, ew, E);
    dinv_kernel<<<cdiv(N, 256), 256>>>(N);
    scan_kernel<<<1, 1024>>>(N);
    fill_kernel<<<cdiv(E, 256), 256>>>(ew, E);

    int gemm_blocks = cdiv(N, 128);
    int agg_blocks = cdiv(N, 8);      // 8 warps per 256-thread block

    // ---- layer 1 ----
    gemm_kernel<FIN, HID, 8><<<gemm_blocks, 256>>>(x, W1, p_ha, N);
    agg_kernel<HID, true><<<agg_blocks, 256>>>(p_ha, b1, p_hb, N);
    // ---- layer 2 ----
    gemm_kernel<HID, HID, 8><<<gemm_blocks, 256>>>(p_hb, W2, p_ha, N);
    agg_kernel<HID, true><<<agg_blocks, 256>>>(p_ha, b2, p_hb, N);
    // ---- layer 3 ----
    gemm_kernel<HID, FOUT, 4><<<gemm_blocks, 256>>>(p_hb, W3, p_ha, N);
    agg_kernel<FOUT, false><<<agg_blocks, 256>>>(p_ha, b3, out, N);

    // ---- mean pool (only if d_out has room for the graph embedding) ----
    if (out_size >= N * FOUT + FOUT) {
        pool1_kernel<<<256, 256>>>(out, N);
        pool2_kernel<<<1, 32>>>(out, N);
    }
}